// round 10
// baseline (speedup 1.0000x reference)
#include <cuda_runtime.h>
#include <cuda_fp16.h>
#include <math.h>
#include <stdint.h>

#define BB 8
#define N1 8192
#define N2 2048
#define C1 128
#define C2 256
#define KIN1 384
#define O1 256
#define O2 128
#define BN_EPS 1e-5f
#define MIN_DIST 1e-10f
#define P_TOTAL (BB * N1)

// ---------------- scratch (no allocations allowed) ----------------
__device__ __half g_p2Th[BB * N2 * C2];               // points2 transposed [B][N2][C2], fp16
__device__ int   g_knn_idx[BB * N1 * 3];
__device__ float g_knn_w[BB * N1 * 3];
__device__ __half g_w0[O1 * KIN1];
__device__ __half g_w1[O2 * O1];
__device__ __half g_x0[BB * N1 * KIN1];               // conv0 B operand [n][k] fp16
__device__ __half g_x2[BB * N1 * O1];                 // conv1 B operand [n][k] fp16
__device__ __half g_y1Th[BB * N1 * O1];               // conv0 out (pre-BN) fp16, [n][o]
__device__ float g_y2[BB * O2 * N1];                  // conv1 out (pre-BN), channel-major [o][n]
__device__ float g_sum0[O1], g_sq0[O1], g_sum1[O2], g_sq1[O2];
__device__ float g_scale0[O1], g_shift0[O1], g_scale1[O2], g_shift1[O2];

// ---------------- helpers ----------------
__device__ __forceinline__ uint32_t smem_u32(const void* p) {
    return (uint32_t)__cvta_generic_to_shared(p);
}
__device__ __forceinline__ void cp16(uint32_t dst, const void* src) {
    asm volatile("cp.async.ca.shared.global [%0], [%1], 16;" :: "r"(dst), "l"(src));
}
__device__ __forceinline__ void cp_commit() {
    asm volatile("cp.async.commit_group;" ::: "memory");
}
template <int N>
__device__ __forceinline__ void cp_wait() {
    asm volatile("cp.async.wait_group %0;" :: "n"(N) : "memory");
}
__device__ __forceinline__ void ldmx4(uint32_t a, uint32_t& r0, uint32_t& r1,
                                      uint32_t& r2, uint32_t& r3) {
    asm volatile("ldmatrix.sync.aligned.m8n8.x4.shared.b16 {%0,%1,%2,%3}, [%4];"
                 : "=r"(r0), "=r"(r1), "=r"(r2), "=r"(r3) : "r"(a));
}
__device__ __forceinline__ void mma16816(float* c, const uint32_t* a,
                                         uint32_t b0, uint32_t b1) {
    asm volatile("mma.sync.aligned.m16n8k16.row.col.f32.f16.f16.f32 "
                 "{%0,%1,%2,%3},{%4,%5,%6,%7},{%8,%9},{%0,%1,%2,%3};"
                 : "+f"(c[0]), "+f"(c[1]), "+f"(c[2]), "+f"(c[3])
                 : "r"(a[0]), "r"(a[1]), "r"(a[2]), "r"(a[3]), "r"(b0), "r"(b1));
}

// ---------------- weights convert + stats zero (one launch; graph replays!) ----------------
__global__ void cvt_w_kernel(const float* __restrict__ w0s,
                             const float* __restrict__ w1s) {
    int i = blockIdx.x * blockDim.x + threadIdx.x;
    if (i < O1 * KIN1) g_w0[i] = __float2half_rn(w0s[i]);
    if (i < O2 * O1)   g_w1[i] = __float2half_rn(w1s[i]);
    if (i < O1) { g_sum0[i] = 0.f; g_sq0[i] = 0.f; }
    if (i < O2) { g_sum1[i] = 0.f; g_sq1[i] = 0.f; }
}

// ---------------- transpose points2 [B,C2,N2] -> fp16 [B,N2,C2] ----------------
__global__ __launch_bounds__(256) void transpose_p2_kernel(const float* __restrict__ p2) {
    __shared__ float tile[64][33];
    int b = blockIdx.z, c0 = blockIdx.y * 64, n0 = blockIdx.x * 32;
    int tx = threadIdx.x & 31, ty = threadIdx.x >> 5;
    #pragma unroll
    for (int i = ty; i < 64; i += 8)
        tile[i][tx] = p2[(size_t)b * C2 * N2 + (size_t)(c0 + i) * N2 + n0 + tx];
    __syncthreads();
    #pragma unroll
    for (int i = 0; i < 4; i++) {
        int n = ty * 4 + i;
        __half h0 = __float2half_rn(tile[tx * 2][n]);
        __half h1 = __float2half_rn(tile[tx * 2 + 1][n]);
        uint32_t pk = (uint32_t)__half_as_ushort(h0) | ((uint32_t)__half_as_ushort(h1) << 16);
        *(uint32_t*)&g_p2Th[((size_t)b * N2 + n0 + n) * C2 + c0 + tx * 2] = pk;
    }
}

// ---------------- transpose+cvt points1 [B,C1,N1] -> x0 [n][0..127] fp16 ----------------
__global__ __launch_bounds__(256) void transpose_p1_kernel(const float* __restrict__ p1) {
    __shared__ float tile[64][33];
    int b = blockIdx.z, c0 = blockIdx.y * 64, n0 = blockIdx.x * 32;
    int tx = threadIdx.x & 31, ty = threadIdx.x >> 5;
    #pragma unroll
    for (int i = ty; i < 64; i += 8)
        tile[i][tx] = p1[(size_t)b * C1 * N1 + (size_t)(c0 + i) * N1 + n0 + tx];
    __syncthreads();
    #pragma unroll
    for (int i = 0; i < 4; i++) {
        int n = ty * 4 + i;
        __half h0 = __float2half_rn(tile[tx * 2][n]);
        __half h1 = __float2half_rn(tile[tx * 2 + 1][n]);
        uint32_t pk = (uint32_t)__half_as_ushort(h0) | ((uint32_t)__half_as_ushort(h1) << 16);
        *(uint32_t*)&g_x0[((size_t)b * N1 + n0 + n) * KIN1 + c0 + tx * 2] = pk;
    }
}

// ---------------- 3-NN: 1 query/thread (proven grid), rank by r = 0.5|p|^2 - q.p ----------------
__global__ __launch_bounds__(128) void knn_kernel(const float* __restrict__ xyz1,
                                                  const float* __restrict__ xyz2) {
    __shared__ float4 s_p[N2];   // (x, y, z, 0.5*|p|^2)
    int b  = blockIdx.x >> 6;
    int n0 = (blockIdx.x & 63) << 7;
    const float* x2 = xyz2 + (size_t)b * N2 * 3;
    for (int j = threadIdx.x; j < N2; j += 128) {
        float px = x2[j * 3], py = x2[j * 3 + 1], pz = x2[j * 3 + 2];
        s_p[j] = make_float4(px, py, pz, 0.5f * (px * px + py * py + pz * pz));
    }
    __syncthreads();
    int n = n0 + threadIdx.x;
    const float* q = xyz1 + ((size_t)b * N1 + n) * 3;
    float qx = q[0], qy = q[1], qz = q[2];
    float r0 = 3.4e38f, r1 = 3.4e38f, r2 = 3.4e38f;
    int   i0 = 0, i1 = 0, i2 = 0;
    #pragma unroll 4
    for (int j = 0; j < N2; j++) {
        float4 p = s_p[j];
        float r = fmaf(-qx, p.x, fmaf(-qy, p.y, fmaf(-qz, p.z, p.w)));
        if (r < r2) {
            if (r < r1) {
                r2 = r1; i2 = i1;
                if (r < r0) { r1 = r0; i1 = i0; r0 = r; i0 = j; }
                else        { r1 = r; i1 = j; }
            } else { r2 = r; i2 = j; }
        }
    }
    float qn = qx * qx + qy * qy + qz * qz;
    float e0 = fmaxf(sqrtf(fmaxf(qn + 2.f * r0, 0.f)), MIN_DIST);
    float e1 = fmaxf(sqrtf(fmaxf(qn + 2.f * r1, 0.f)), MIN_DIST);
    float e2 = fmaxf(sqrtf(fmaxf(qn + 2.f * r2, 0.f)), MIN_DIST);
    float w0 = 1.f / e0, w1 = 1.f / e1, w2 = 1.f / e2;
    float inv = 1.f / (w0 + w1 + w2);
    size_t on = ((size_t)b * N1 + n) * 3;
    g_knn_idx[on] = i0; g_knn_idx[on + 1] = i1; g_knn_idx[on + 2] = i2;
    g_knn_w[on] = w0 * inv; g_knn_w[on + 1] = w1 * inv; g_knn_w[on + 2] = w2 * inv;
}

// ---------------- interpolation (fp16 gather) -> x0 [n][128..383] fp16 ----------------
__global__ __launch_bounds__(256) void interp_kernel() {
    __shared__ int   s_idx[96];
    __shared__ float s_w[96];
    int b  = blockIdx.x >> 8;
    int n0 = (blockIdx.x & 255) << 5;
    int t  = threadIdx.x;
    if (t < 96) {
        size_t base = ((size_t)b * N1 + n0) * 3 + t;
        s_idx[t] = g_knn_idx[base];
        s_w[t]   = g_knn_w[base];
    }
    __syncthreads();
    int c = t;
    #pragma unroll 8
    for (int p = 0; p < 32; p++) {
        int k = p * 3;
        const __half* r0 = g_p2Th + ((size_t)b * N2 + s_idx[k + 0]) * C2 + c;
        const __half* r1 = g_p2Th + ((size_t)b * N2 + s_idx[k + 1]) * C2 + c;
        const __half* r2 = g_p2Th + ((size_t)b * N2 + s_idx[k + 2]) * C2 + c;
        float v = fmaf(s_w[k], __half2float(*r0),
                  fmaf(s_w[k + 1], __half2float(*r1),
                       s_w[k + 2] * __half2float(*r2)));
        g_x0[((size_t)b * N1 + n0 + p) * KIN1 + C1 + c] = __float2half_rn(v);
    }
}

// ---------------- mma.sync conv, single-pass fp16 ----------------
// CTA 128x128, 8 warps (2x4 -> 64x32 each), K-chunk 64, cp.async double buffer.
// SMEM rows padded to 72 fp16 (144 B) -> conflict-free ldmatrix.
// NOTE: mainloop is proven; do not touch. (256,2) spills accumulators (R7).
#define SM_A0 0
#define SM_A1 18432
#define SM_B0 36864
#define SM_B1 55296
#define SMEM_MMA 73728

template <int LAYER>
__global__ void __launch_bounds__(256, 1) conv_mma_kernel(const float* __restrict__ bias) {
    constexpr int K   = (LAYER == 0) ? KIN1 : O1;
    constexpr int NCH = K / 64;
    extern __shared__ char smem[];
    uint32_t sb = smem_u32(smem);

    int tid  = threadIdx.x;
    int lane = tid & 31, wid = tid >> 5;
    int m_off = (wid >> 2) * 64;     // warp m-origin (o)
    int n_off = (wid & 3) * 32;      // warp n-origin (points)
    int b  = blockIdx.x >> 6;
    int n0 = (blockIdx.x & 63) << 7;
    int o0 = blockIdx.y << 7;

    const __half* Wbase = ((LAYER == 0) ? g_w0 : g_w1) + (size_t)o0 * K;
    const __half* Xbase = ((LAYER == 0) ? g_x0 : g_x2) + ((size_t)b * N1 + n0) * K;

    uint32_t lm_off = (uint32_t)(((lane & 7) + ((lane >> 3) & 1) * 8) * 144 + (lane >> 4) * 16);

    float acc[4][4][4];
    #pragma unroll
    for (int mi = 0; mi < 4; mi++)
        #pragma unroll
        for (int ni = 0; ni < 4; ni++)
            #pragma unroll
            for (int r = 0; r < 4; r++) acc[mi][ni][r] = 0.f;

    int ld_row = tid >> 3;           // 32 rows per i-step
    int ld_seg = tid & 7;

    auto issue_chunk = [&](int c, int buf) {
        int kk = c * 64;
        uint32_t A  = sb + (buf ? SM_A1 : SM_A0);
        uint32_t Bf = sb + (buf ? SM_B1 : SM_B0);
        #pragma unroll
        for (int i = 0; i < 4; i++) {
            int row = ld_row + i * 32;
            uint32_t d = (uint32_t)(row * 144 + ld_seg * 16);
            cp16(A + d,  Wbase + (size_t)row * K + kk + ld_seg * 8);
            cp16(Bf + d, Xbase + (size_t)row * K + kk + ld_seg * 8);
        }
        cp_commit();
    };

    issue_chunk(0, 0);
    for (int c = 0; c < NCH; c++) {
        int buf = c & 1;
        if (c + 1 < NCH) { issue_chunk(c + 1, buf ^ 1); cp_wait<1>(); }
        else             { cp_wait<0>(); }
        __syncthreads();

        uint32_t A  = sb + (buf ? SM_A1 : SM_A0) + (uint32_t)(m_off * 144) + lm_off;
        uint32_t Bf = sb + (buf ? SM_B1 : SM_B0) + (uint32_t)(n_off * 144) + lm_off;
        #pragma unroll
        for (int kst = 0; kst < 4; kst++) {
            uint32_t af[4][4], bf[2][4];
            #pragma unroll
            for (int mi = 0; mi < 4; mi++)
                ldmx4(A + (uint32_t)(mi * 16 * 144 + kst * 32),
                      af[mi][0], af[mi][1], af[mi][2], af[mi][3]);
            #pragma unroll
            for (int nj = 0; nj < 2; nj++)
                ldmx4(Bf + (uint32_t)(nj * 16 * 144 + kst * 32),
                      bf[nj][0], bf[nj][1], bf[nj][2], bf[nj][3]);
            #pragma unroll
            for (int mi = 0; mi < 4; mi++)
                #pragma unroll
                for (int ni = 0; ni < 4; ni++)
                    mma16816(acc[mi][ni], af[mi],
                             bf[ni >> 1][ni & 1], bf[ni >> 1][(ni & 1) + 2]);
        }
        __syncthreads();
    }

    // ---- epilogue: stage D to SMEM [o][n] stride 129, then stats + stores ----
    float* sD = (float*)smem;
    #pragma unroll
    for (int mi = 0; mi < 4; mi++) {
        int r0 = m_off + mi * 16 + (lane >> 2);
        #pragma unroll
        for (int ni = 0; ni < 4; ni++) {
            int cc = n_off + ni * 8 + (lane & 3) * 2;
            sD[r0 * 129 + cc]           = acc[mi][ni][0];
            sD[r0 * 129 + cc + 1]       = acc[mi][ni][1];
            sD[(r0 + 8) * 129 + cc]     = acc[mi][ni][2];
            sD[(r0 + 8) * 129 + cc + 1] = acc[mi][ni][3];
        }
    }
    __syncthreads();

    {
        int o = tid & 127;
        int nlo = (tid >> 7) * 64;
        float bi = bias[o0 + o];
        float s = 0.f, s2 = 0.f;
        #pragma unroll 4
        for (int n = nlo; n < nlo + 64; n++) {
            float v = sD[o * 129 + n] + bi;
            s += v;
            s2 = fmaf(v, v, s2);
        }
        float* gs = (LAYER == 0) ? g_sum0 : g_sum1;
        float* gq = (LAYER == 0) ? g_sq0  : g_sq1;
        atomicAdd(&gs[o0 + o], s);
        atomicAdd(&gq[o0 + o], s2);
    }

    if (LAYER == 0) {
        // fp16 packed-pair stores: y1Th[n][o], 128B/warp
        for (int e = tid; e < 128 * 64; e += 256) {
            int n = e >> 6, op = e & 63;
            float v0 = sD[(2 * op) * 129 + n]     + bias[o0 + 2 * op];
            float v1 = sD[(2 * op + 1) * 129 + n] + bias[o0 + 2 * op + 1];
            uint32_t pk = (uint32_t)__half_as_ushort(__float2half_rn(v0))
                        | ((uint32_t)__half_as_ushort(__float2half_rn(v1)) << 16);
            *(uint32_t*)&g_y1Th[((size_t)b * N1 + n0 + n) * O1 + o0 + 2 * op] = pk;
        }
    } else {
        for (int e = tid; e < 128 * 128; e += 256) {
            int o = e >> 7, n = e & 127;
            g_y2[((size_t)b * O2 + o) * N1 + n0 + n] = sD[o * 129 + n] + bias[o];
        }
    }
}

// ---------------- BN finalize ----------------
template <int LAYER>
__global__ void bn_finalize_kernel(const float* __restrict__ gamma,
                                   const float* __restrict__ beta) {
    constexpr int O = (LAYER == 0) ? O1 : O2;
    int o = threadIdx.x;
    if (o < O) {
        const float inv = 1.0f / (float)P_TOTAL;
        float su = (LAYER == 0) ? g_sum0[o] : g_sum1[o];
        float sq = (LAYER == 0) ? g_sq0[o]  : g_sq1[o];
        float mu  = su * inv;
        float var = sq * inv - mu * mu;
        float sc  = gamma[o] * rsqrtf(var + BN_EPS);
        if (LAYER == 0) { g_scale0[o] = sc; g_shift0[o] = beta[o] - mu * sc; }
        else            { g_scale1[o] = sc; g_shift1[o] = beta[o] - mu * sc; }
    }
}

// ---------------- midpass: y1Th (fp16) -> BN0+ReLU -> x2 fp16 ----------------
__global__ __launch_bounds__(256) void midpass_kernel() {
    size_t i8 = (size_t)blockIdx.x * 256 + threadIdx.x;   // uint4 index (8 halves)
    uint4 v = ((const uint4*)g_y1Th)[i8];
    int c0 = (int)((i8 * 8) & (O1 - 1));
    uint32_t in[4] = {v.x, v.y, v.z, v.w};
    uint32_t outw[4];
    #pragma unroll
    for (int j = 0; j < 4; j++) {
        float a0 = __half2float(__ushort_as_half((unsigned short)(in[j] & 0xFFFF)));
        float a1 = __half2float(__ushort_as_half((unsigned short)(in[j] >> 16)));
        float x0 = fmaxf(fmaf(a0, g_scale0[c0 + 2 * j],     g_shift0[c0 + 2 * j]),     0.f);
        float x1 = fmaxf(fmaf(a1, g_scale0[c0 + 2 * j + 1], g_shift0[c0 + 2 * j + 1]), 0.f);
        outw[j] = (uint32_t)__half_as_ushort(__float2half_rn(x0))
                | ((uint32_t)__half_as_ushort(__float2half_rn(x1)) << 16);
    }
    ((uint4*)g_x2)[i8] = make_uint4(outw[0], outw[1], outw[2], outw[3]);
}

// ---------------- final BN1 + ReLU -> output ----------------
__global__ __launch_bounds__(256) void final_kernel(float* __restrict__ out) {
    int i = blockIdx.x * blockDim.x + threadIdx.x;
    float4 v = ((const float4*)g_y2)[i];
    int c = ((i * 4) / N1) & (O2 - 1);
    float sc = g_scale1[c], sh = g_shift1[c];
    v.x = fmaxf(fmaf(v.x, sc, sh), 0.f);
    v.y = fmaxf(fmaf(v.y, sc, sh), 0.f);
    v.z = fmaxf(fmaf(v.z, sc, sh), 0.f);
    v.w = fmaxf(fmaf(v.w, sc, sh), 0.f);
    ((float4*)out)[i] = v;
}

// ---------------- launch ----------------
extern "C" void kernel_launch(void* const* d_in, const int* in_sizes, int n_in,
                              void* d_out, int out_size) {
    const float* xyz1    = (const float*)d_in[0];
    const float* xyz2    = (const float*)d_in[1];
    const float* points1 = (const float*)d_in[2];
    const float* points2 = (const float*)d_in[3];
    const float* w0  = (const float*)d_in[4];
    const float* b0  = (const float*)d_in[5];
    const float* ga0 = (const float*)d_in[6];
    const float* be0 = (const float*)d_in[7];
    const float* w1  = (const float*)d_in[8];
    const float* b1  = (const float*)d_in[9];
    const float* ga1 = (const float*)d_in[10];
    const float* be1 = (const float*)d_in[11];
    float* out = (float*)d_out;

    cudaFuncSetAttribute(conv_mma_kernel<0>, cudaFuncAttributeMaxDynamicSharedMemorySize, SMEM_MMA);
    cudaFuncSetAttribute(conv_mma_kernel<1>, cudaFuncAttributeMaxDynamicSharedMemorySize, SMEM_MMA);

    cvt_w_kernel<<<(O1 * KIN1 + 255) / 256, 256>>>(w0, w1);
    transpose_p2_kernel<<<dim3(N2 / 32, C2 / 64, BB), 256>>>(points2);
    transpose_p1_kernel<<<dim3(N1 / 32, C1 / 64, BB), 256>>>(points1);
    knn_kernel<<<BB * (N1 / 128), 128>>>(xyz1, xyz2);
    interp_kernel<<<BB * (N1 / 32), 256>>>();
    conv_mma_kernel<0><<<dim3(BB * (N1 / 128), O1 / 128), 256, SMEM_MMA>>>(b0);
    bn_finalize_kernel<0><<<1, 256>>>(ga0, be0);
    midpass_kernel<<<(BB * N1 * O1 / 8) / 256, 256>>>();
    conv_mma_kernel<1><<<dim3(BB * (N1 / 128), O2 / 128), 256, SMEM_MMA>>>(b1);
    bn_finalize_kernel<1><<<1, 128>>>(ga1, be1);
    final_kernel<<<(BB * O2 * N1 / 4) / 256, 256>>>(out);
}

// round 11
// speedup vs baseline: 1.1019x; 1.1019x over previous
#include <cuda_runtime.h>
#include <cuda_fp16.h>
#include <math.h>
#include <stdint.h>

#define BB 8
#define N1 8192
#define N2 2048
#define C1 128
#define C2 256
#define KIN1 384
#define O1 256
#define O2 128
#define BN_EPS 1e-5f
#define MIN_DIST 1e-10f
#define P_TOTAL (BB * N1)

// ---------------- scratch (no allocations allowed) ----------------
__device__ __half g_p2Th[BB * N2 * C2];               // points2 transposed [B][N2][C2], fp16
__device__ int   g_knn_idx[BB * N1 * 3];
__device__ float g_knn_w[BB * N1 * 3];
__device__ __half g_w0[O1 * KIN1];
__device__ __half g_w1[O2 * O1];
__device__ __half g_x0[BB * N1 * KIN1];               // conv0 B operand [n][k] fp16
__device__ __half g_x2[BB * N1 * O1];                 // conv1 B operand [n][k] fp16
__device__ float g_y1T[BB * N1 * O1];                 // conv0 out (pre-BN) fp32, [n][o]
__device__ float g_y2[BB * O2 * N1];                  // conv1 out (pre-BN), channel-major [o][n]
__device__ float g_sum0[O1], g_sq0[O1], g_sum1[O2], g_sq1[O2];
__device__ float g_scale0[O1], g_shift0[O1], g_scale1[O2], g_shift1[O2];

// ---------------- helpers ----------------
__device__ __forceinline__ uint32_t smem_u32(const void* p) {
    return (uint32_t)__cvta_generic_to_shared(p);
}
__device__ __forceinline__ void cp16(uint32_t dst, const void* src) {
    asm volatile("cp.async.ca.shared.global [%0], [%1], 16;" :: "r"(dst), "l"(src));
}
__device__ __forceinline__ void cp_commit() {
    asm volatile("cp.async.commit_group;" ::: "memory");
}
template <int N>
__device__ __forceinline__ void cp_wait() {
    asm volatile("cp.async.wait_group %0;" :: "n"(N) : "memory");
}
__device__ __forceinline__ void ldmx4(uint32_t a, uint32_t& r0, uint32_t& r1,
                                      uint32_t& r2, uint32_t& r3) {
    asm volatile("ldmatrix.sync.aligned.m8n8.x4.shared.b16 {%0,%1,%2,%3}, [%4];"
                 : "=r"(r0), "=r"(r1), "=r"(r2), "=r"(r3) : "r"(a));
}
__device__ __forceinline__ void mma16816(float* c, const uint32_t* a,
                                         uint32_t b0, uint32_t b1) {
    asm volatile("mma.sync.aligned.m16n8k16.row.col.f32.f16.f16.f32 "
                 "{%0,%1,%2,%3},{%4,%5,%6,%7},{%8,%9},{%0,%1,%2,%3};"
                 : "+f"(c[0]), "+f"(c[1]), "+f"(c[2]), "+f"(c[3])
                 : "r"(a[0]), "r"(a[1]), "r"(a[2]), "r"(a[3]), "r"(b0), "r"(b1));
}
__device__ __forceinline__ bool knn_lt(float ra, int ia, float rb, int ib) {
    return (ra < rb) || (ra == rb && ia < ib);
}

// ---------------- weights convert + stats zero (one launch; graph replays!) ----------------
__global__ void cvt_w_kernel(const float* __restrict__ w0s,
                             const float* __restrict__ w1s) {
    int i = blockIdx.x * blockDim.x + threadIdx.x;
    if (i < O1 * KIN1) g_w0[i] = __float2half_rn(w0s[i]);
    if (i < O2 * O1)   g_w1[i] = __float2half_rn(w1s[i]);
    if (i < O1) { g_sum0[i] = 0.f; g_sq0[i] = 0.f; }
    if (i < O2) { g_sum1[i] = 0.f; g_sq1[i] = 0.f; }
}

// ---------------- transpose points2 [B,C2,N2] -> fp16 [B,N2,C2] ----------------
__global__ __launch_bounds__(256) void transpose_p2_kernel(const float* __restrict__ p2) {
    __shared__ float tile[64][33];
    int b = blockIdx.z, c0 = blockIdx.y * 64, n0 = blockIdx.x * 32;
    int tx = threadIdx.x & 31, ty = threadIdx.x >> 5;
    #pragma unroll
    for (int i = ty; i < 64; i += 8)
        tile[i][tx] = p2[(size_t)b * C2 * N2 + (size_t)(c0 + i) * N2 + n0 + tx];
    __syncthreads();
    #pragma unroll
    for (int i = 0; i < 4; i++) {
        int n = ty * 4 + i;
        __half h0 = __float2half_rn(tile[tx * 2][n]);
        __half h1 = __float2half_rn(tile[tx * 2 + 1][n]);
        uint32_t pk = (uint32_t)__half_as_ushort(h0) | ((uint32_t)__half_as_ushort(h1) << 16);
        *(uint32_t*)&g_p2Th[((size_t)b * N2 + n0 + n) * C2 + c0 + tx * 2] = pk;
    }
}

// ---------------- transpose+cvt points1 [B,C1,N1] -> x0 [n][0..127] fp16 ----------------
__global__ __launch_bounds__(256) void transpose_p1_kernel(const float* __restrict__ p1) {
    __shared__ float tile[64][33];
    int b = blockIdx.z, c0 = blockIdx.y * 64, n0 = blockIdx.x * 32;
    int tx = threadIdx.x & 31, ty = threadIdx.x >> 5;
    #pragma unroll
    for (int i = ty; i < 64; i += 8)
        tile[i][tx] = p1[(size_t)b * C1 * N1 + (size_t)(c0 + i) * N1 + n0 + tx];
    __syncthreads();
    #pragma unroll
    for (int i = 0; i < 4; i++) {
        int n = ty * 4 + i;
        __half h0 = __float2half_rn(tile[tx * 2][n]);
        __half h1 = __float2half_rn(tile[tx * 2 + 1][n]);
        uint32_t pk = (uint32_t)__half_as_ushort(h0) | ((uint32_t)__half_as_ushort(h1) << 16);
        *(uint32_t*)&g_x0[((size_t)b * N1 + n0 + n) * KIN1 + c0 + tx * 2] = pk;
    }
}

// ---------------- 3-NN: 4 lanes per query (N2 split), shfl merge ----------------
// 256 threads = 64 queries/block; warp = 8 queries x 4 segment-lanes.
// Lane seg scans j = 4*jj + seg (interleaved -> conflict-free 64B spans).
// Rank by r = 0.5|p|^2 - q.p; merge by (r, idx) lexicographic == sequential strict-<.
__global__ __launch_bounds__(256) void knn_kernel(const float* __restrict__ xyz1,
                                                  const float* __restrict__ xyz2) {
    __shared__ float4 s_p[N2];   // (x, y, z, 0.5*|p|^2)
    int b  = blockIdx.x >> 7;            // 128 blocks per batch
    int n0 = (blockIdx.x & 127) << 6;    // 64 queries per block
    const float* x2 = xyz2 + (size_t)b * N2 * 3;
    for (int j = threadIdx.x; j < N2; j += 256) {
        float px = x2[j * 3], py = x2[j * 3 + 1], pz = x2[j * 3 + 2];
        s_p[j] = make_float4(px, py, pz, 0.5f * (px * px + py * py + pz * pz));
    }
    __syncthreads();

    int t = threadIdx.x;
    int w = t >> 5, lane = t & 31;
    int seg = lane >> 3;                 // 0..3
    int n = n0 + w * 8 + (lane & 7);
    const float* q = xyz1 + ((size_t)b * N1 + n) * 3;
    float qx = q[0], qy = q[1], qz = q[2];

    float r0 = 3.4e38f, r1 = 3.4e38f, r2 = 3.4e38f;
    int   i0 = 0, i1 = 0, i2 = 0;
    #pragma unroll 4
    for (int jj = 0; jj < N2 / 4; jj++) {
        int j = (jj << 2) | seg;
        float4 p = s_p[j];
        float r = fmaf(-qx, p.x, fmaf(-qy, p.y, fmaf(-qz, p.z, p.w)));
        if (r < r2) {
            if (r < r1) {
                r2 = r1; i2 = i1;
                if (r < r0) { r1 = r0; i1 = i0; r0 = r; i0 = j; }
                else        { r1 = r; i1 = j; }
            } else { r2 = r; i2 = j; }
        }
    }

    // merge the 4 segment-lane triples: xor 8, then xor 16
    #pragma unroll
    for (int m = 8; m <= 16; m <<= 1) {
        float s0 = __shfl_xor_sync(0xffffffff, r0, m);
        float s1 = __shfl_xor_sync(0xffffffff, r1, m);
        float s2 = __shfl_xor_sync(0xffffffff, r2, m);
        int   j0 = __shfl_xor_sync(0xffffffff, i0, m);
        int   j1 = __shfl_xor_sync(0xffffffff, i1, m);
        int   j2 = __shfl_xor_sync(0xffffffff, i2, m);
        float c0, c1, c2; int d0, d1, d2;
        if (knn_lt(r0, i0, s0, j0)) {
            c0 = r0; d0 = i0;
            if (knn_lt(r1, i1, s0, j0)) {
                c1 = r1; d1 = i1;
                if (knn_lt(r2, i2, s0, j0)) { c2 = r2; d2 = i2; }
                else                        { c2 = s0; d2 = j0; }
            } else {
                c1 = s0; d1 = j0;
                if (knn_lt(r1, i1, s1, j1)) { c2 = r1; d2 = i1; }
                else                        { c2 = s1; d2 = j1; }
            }
        } else {
            c0 = s0; d0 = j0;
            if (knn_lt(s1, j1, r0, i0)) {
                c1 = s1; d1 = j1;
                if (knn_lt(s2, j2, r0, i0)) { c2 = s2; d2 = j2; }
                else                        { c2 = r0; d2 = i0; }
            } else {
                c1 = r0; d1 = i0;
                if (knn_lt(r1, i1, s1, j1)) { c2 = r1; d2 = i1; }
                else                        { c2 = s1; d2 = j1; }
            }
        }
        r0 = c0; r1 = c1; r2 = c2; i0 = d0; i1 = d1; i2 = d2;
    }

    if (seg == 0) {
        float qn = qx * qx + qy * qy + qz * qz;
        float e0 = fmaxf(sqrtf(fmaxf(qn + 2.f * r0, 0.f)), MIN_DIST);
        float e1 = fmaxf(sqrtf(fmaxf(qn + 2.f * r1, 0.f)), MIN_DIST);
        float e2 = fmaxf(sqrtf(fmaxf(qn + 2.f * r2, 0.f)), MIN_DIST);
        float w0 = 1.f / e0, w1 = 1.f / e1, w2 = 1.f / e2;
        float inv = 1.f / (w0 + w1 + w2);
        size_t on = ((size_t)b * N1 + n) * 3;
        g_knn_idx[on] = i0; g_knn_idx[on + 1] = i1; g_knn_idx[on + 2] = i2;
        g_knn_w[on] = w0 * inv; g_knn_w[on + 1] = w1 * inv; g_knn_w[on + 2] = w2 * inv;
    }
}

// ---------------- interpolation (fp16 gather) -> x0 [n][128..383] fp16 ----------------
__global__ __launch_bounds__(256) void interp_kernel() {
    __shared__ int   s_idx[96];
    __shared__ float s_w[96];
    int b  = blockIdx.x >> 8;
    int n0 = (blockIdx.x & 255) << 5;
    int t  = threadIdx.x;
    if (t < 96) {
        size_t base = ((size_t)b * N1 + n0) * 3 + t;
        s_idx[t] = g_knn_idx[base];
        s_w[t]   = g_knn_w[base];
    }
    __syncthreads();
    int c = t;
    #pragma unroll 8
    for (int p = 0; p < 32; p++) {
        int k = p * 3;
        const __half* r0 = g_p2Th + ((size_t)b * N2 + s_idx[k + 0]) * C2 + c;
        const __half* r1 = g_p2Th + ((size_t)b * N2 + s_idx[k + 1]) * C2 + c;
        const __half* r2 = g_p2Th + ((size_t)b * N2 + s_idx[k + 2]) * C2 + c;
        float v = fmaf(s_w[k], __half2float(*r0),
                  fmaf(s_w[k + 1], __half2float(*r1),
                       s_w[k + 2] * __half2float(*r2)));
        g_x0[((size_t)b * N1 + n0 + p) * KIN1 + C1 + c] = __float2half_rn(v);
    }
}

// ---------------- mma.sync conv, single-pass fp16 ----------------
// CTA 128x128, 8 warps (2x4 -> 64x32 each), K-chunk 64, cp.async double buffer.
// SMEM rows padded to 72 fp16 (144 B) -> conflict-free ldmatrix.
// NOTE: mainloop is proven; do not touch. (256,2) spills accumulators (R7).
#define SM_A0 0
#define SM_A1 18432
#define SM_B0 36864
#define SM_B1 55296
#define SMEM_MMA 73728

template <int LAYER>
__global__ void __launch_bounds__(256, 1) conv_mma_kernel(const float* __restrict__ bias) {
    constexpr int K   = (LAYER == 0) ? KIN1 : O1;
    constexpr int NCH = K / 64;
    extern __shared__ char smem[];
    uint32_t sb = smem_u32(smem);

    int tid  = threadIdx.x;
    int lane = tid & 31, wid = tid >> 5;
    int m_off = (wid >> 2) * 64;     // warp m-origin (o)
    int n_off = (wid & 3) * 32;      // warp n-origin (points)
    int b  = blockIdx.x >> 6;
    int n0 = (blockIdx.x & 63) << 7;
    int o0 = blockIdx.y << 7;

    const __half* Wbase = ((LAYER == 0) ? g_w0 : g_w1) + (size_t)o0 * K;
    const __half* Xbase = ((LAYER == 0) ? g_x0 : g_x2) + ((size_t)b * N1 + n0) * K;

    uint32_t lm_off = (uint32_t)(((lane & 7) + ((lane >> 3) & 1) * 8) * 144 + (lane >> 4) * 16);

    float acc[4][4][4];
    #pragma unroll
    for (int mi = 0; mi < 4; mi++)
        #pragma unroll
        for (int ni = 0; ni < 4; ni++)
            #pragma unroll
            for (int r = 0; r < 4; r++) acc[mi][ni][r] = 0.f;

    int ld_row = tid >> 3;           // 32 rows per i-step
    int ld_seg = tid & 7;

    auto issue_chunk = [&](int c, int buf) {
        int kk = c * 64;
        uint32_t A  = sb + (buf ? SM_A1 : SM_A0);
        uint32_t Bf = sb + (buf ? SM_B1 : SM_B0);
        #pragma unroll
        for (int i = 0; i < 4; i++) {
            int row = ld_row + i * 32;
            uint32_t d = (uint32_t)(row * 144 + ld_seg * 16);
            cp16(A + d,  Wbase + (size_t)row * K + kk + ld_seg * 8);
            cp16(Bf + d, Xbase + (size_t)row * K + kk + ld_seg * 8);
        }
        cp_commit();
    };

    issue_chunk(0, 0);
    for (int c = 0; c < NCH; c++) {
        int buf = c & 1;
        if (c + 1 < NCH) { issue_chunk(c + 1, buf ^ 1); cp_wait<1>(); }
        else             { cp_wait<0>(); }
        __syncthreads();

        uint32_t A  = sb + (buf ? SM_A1 : SM_A0) + (uint32_t)(m_off * 144) + lm_off;
        uint32_t Bf = sb + (buf ? SM_B1 : SM_B0) + (uint32_t)(n_off * 144) + lm_off;
        #pragma unroll
        for (int kst = 0; kst < 4; kst++) {
            uint32_t af[4][4], bf[2][4];
            #pragma unroll
            for (int mi = 0; mi < 4; mi++)
                ldmx4(A + (uint32_t)(mi * 16 * 144 + kst * 32),
                      af[mi][0], af[mi][1], af[mi][2], af[mi][3]);
            #pragma unroll
            for (int nj = 0; nj < 2; nj++)
                ldmx4(Bf + (uint32_t)(nj * 16 * 144 + kst * 32),
                      bf[nj][0], bf[nj][1], bf[nj][2], bf[nj][3]);
            #pragma unroll
            for (int mi = 0; mi < 4; mi++)
                #pragma unroll
                for (int ni = 0; ni < 4; ni++)
                    mma16816(acc[mi][ni], af[mi],
                             bf[ni >> 1][ni & 1], bf[ni >> 1][(ni & 1) + 2]);
        }
        __syncthreads();
    }

    // ---- epilogue: stage D to SMEM [o][n] stride 129, then stats + stores ----
    float* sD = (float*)smem;
    #pragma unroll
    for (int mi = 0; mi < 4; mi++) {
        int r0 = m_off + mi * 16 + (lane >> 2);
        #pragma unroll
        for (int ni = 0; ni < 4; ni++) {
            int cc = n_off + ni * 8 + (lane & 3) * 2;
            sD[r0 * 129 + cc]           = acc[mi][ni][0];
            sD[r0 * 129 + cc + 1]       = acc[mi][ni][1];
            sD[(r0 + 8) * 129 + cc]     = acc[mi][ni][2];
            sD[(r0 + 8) * 129 + cc + 1] = acc[mi][ni][3];
        }
    }
    __syncthreads();

    {
        int o = tid & 127;
        int nlo = (tid >> 7) * 64;
        float bi = bias[o0 + o];
        float s = 0.f, s2 = 0.f;
        #pragma unroll 4
        for (int n = nlo; n < nlo + 64; n++) {
            float v = sD[o * 129 + n] + bi;
            s += v;
            s2 = fmaf(v, v, s2);
        }
        float* gs = (LAYER == 0) ? g_sum0 : g_sum1;
        float* gq = (LAYER == 0) ? g_sq0  : g_sq1;
        atomicAdd(&gs[o0 + o], s);
        atomicAdd(&gq[o0 + o], s2);
    }

    if (LAYER == 0) {
        for (int e = tid; e < 128 * 128; e += 256) {
            int n = e >> 7, o = e & 127;
            g_y1T[((size_t)b * N1 + n0 + n) * O1 + o0 + o] = sD[o * 129 + n] + bias[o0 + o];
        }
    } else {
        for (int e = tid; e < 128 * 128; e += 256) {
            int o = e >> 7, n = e & 127;
            g_y2[((size_t)b * O2 + o) * N1 + n0 + n] = sD[o * 129 + n] + bias[o];
        }
    }
}

// ---------------- BN finalize ----------------
template <int LAYER>
__global__ void bn_finalize_kernel(const float* __restrict__ gamma,
                                   const float* __restrict__ beta) {
    constexpr int O = (LAYER == 0) ? O1 : O2;
    int o = threadIdx.x;
    if (o < O) {
        const float inv = 1.0f / (float)P_TOTAL;
        float su = (LAYER == 0) ? g_sum0[o] : g_sum1[o];
        float sq = (LAYER == 0) ? g_sq0[o]  : g_sq1[o];
        float mu  = su * inv;
        float var = sq * inv - mu * mu;
        float sc  = gamma[o] * rsqrtf(var + BN_EPS);
        if (LAYER == 0) { g_scale0[o] = sc; g_shift0[o] = beta[o] - mu * sc; }
        else            { g_scale1[o] = sc; g_shift1[o] = beta[o] - mu * sc; }
    }
}

// ---------------- midpass: y1T (fp32) -> BN0+ReLU -> x2 fp16 ----------------
__global__ __launch_bounds__(256) void midpass_kernel() {
    size_t i4 = (size_t)blockIdx.x * 256 + threadIdx.x;   // float4 index
    float4 v = ((const float4*)g_y1T)[i4];
    int c0 = (int)((i4 * 4) & (O1 - 1));
    float r[4] = {v.x, v.y, v.z, v.w};
    unsigned short h[4];
    #pragma unroll
    for (int j = 0; j < 4; j++) {
        float x = fmaxf(fmaf(r[j], g_scale0[c0 + j], g_shift0[c0 + j]), 0.f);
        h[j] = __half_as_ushort(__float2half_rn(x));
    }
    ((uint2*)g_x2)[i4] = make_uint2((uint32_t)h[0] | ((uint32_t)h[1] << 16),
                                    (uint32_t)h[2] | ((uint32_t)h[3] << 16));
}

// ---------------- final BN1 + ReLU -> output ----------------
__global__ __launch_bounds__(256) void final_kernel(float* __restrict__ out) {
    int i = blockIdx.x * blockDim.x + threadIdx.x;
    float4 v = ((const float4*)g_y2)[i];
    int c = ((i * 4) / N1) & (O2 - 1);
    float sc = g_scale1[c], sh = g_shift1[c];
    v.x = fmaxf(fmaf(v.x, sc, sh), 0.f);
    v.y = fmaxf(fmaf(v.y, sc, sh), 0.f);
    v.z = fmaxf(fmaf(v.z, sc, sh), 0.f);
    v.w = fmaxf(fmaf(v.w, sc, sh), 0.f);
    ((float4*)out)[i] = v;
}

// ---------------- launch ----------------
extern "C" void kernel_launch(void* const* d_in, const int* in_sizes, int n_in,
                              void* d_out, int out_size) {
    const float* xyz1    = (const float*)d_in[0];
    const float* xyz2    = (const float*)d_in[1];
    const float* points1 = (const float*)d_in[2];
    const float* points2 = (const float*)d_in[3];
    const float* w0  = (const float*)d_in[4];
    const float* b0  = (const float*)d_in[5];
    const float* ga0 = (const float*)d_in[6];
    const float* be0 = (const float*)d_in[7];
    const float* w1  = (const float*)d_in[8];
    const float* b1  = (const float*)d_in[9];
    const float* ga1 = (const float*)d_in[10];
    const float* be1 = (const float*)d_in[11];
    float* out = (float*)d_out;

    cudaFuncSetAttribute(conv_mma_kernel<0>, cudaFuncAttributeMaxDynamicSharedMemorySize, SMEM_MMA);
    cudaFuncSetAttribute(conv_mma_kernel<1>, cudaFuncAttributeMaxDynamicSharedMemorySize, SMEM_MMA);

    cvt_w_kernel<<<(O1 * KIN1 + 255) / 256, 256>>>(w0, w1);
    transpose_p2_kernel<<<dim3(N2 / 32, C2 / 64, BB), 256>>>(points2);
    transpose_p1_kernel<<<dim3(N1 / 32, C1 / 64, BB), 256>>>(points1);
    knn_kernel<<<BB * (N1 / 64), 256>>>(xyz1, xyz2);
    interp_kernel<<<BB * (N1 / 32), 256>>>();
    conv_mma_kernel<0><<<dim3(BB * (N1 / 128), O1 / 128), 256, SMEM_MMA>>>(b0);
    bn_finalize_kernel<0><<<1, 256>>>(ga0, be0);
    midpass_kernel<<<(BB * N1 * O1 / 4) / 256, 256>>>();
    conv_mma_kernel<1><<<dim3(BB * (N1 / 128), O2 / 128), 256, SMEM_MMA>>>(b1);
    bn_finalize_kernel<1><<<1, 128>>>(ga1, be1);
    final_kernel<<<(BB * O2 * N1 / 4) / 256, 256>>>(out);
}